// round 1
// baseline (speedup 1.0000x reference)
#include <cuda_runtime.h>
#include <math.h>

// Problem constants (fixed by reference_code)
#define N_NODES 50000
#define E_EDGES 800000
#define D_IN    256
#define D_HID   256
#define D_OUT_  128

// ---------------- device scratch (no allocations allowed) ----------------
__device__ float g_support1[N_NODES * D_HID];
__device__ float g_gate1   [N_NODES * D_HID];
__device__ float g_out1    [N_NODES * D_HID];
__device__ float g_gagg1   [N_NODES * D_HID];
__device__ float g_h       [N_NODES * D_HID];
__device__ float g_support2[N_NODES * D_OUT_];
__device__ float g_gate2   [N_NODES * D_OUT_];
__device__ float g_gagg2   [N_NODES * D_OUT_];

// ---------------- zero fill ----------------
__global__ void zero_kernel(float* __restrict__ p, int n4) {
    int i = blockIdx.x * blockDim.x + threadIdx.x;
    if (i < n4) {
        ((float4*)p)[i] = make_float4(0.f, 0.f, 0.f, 0.f);
    }
}

// ---------------- tiled SGEMM: C[nrows,M] = A[nrows,K] @ B[K,M] ----------------
// BM=BN=64, BK=16, 256 threads, 4x4 per thread. K multiple of 16, M multiple of 64.
__global__ void sgemm64(const float* __restrict__ A, const float* __restrict__ B,
                        float* __restrict__ C, int nrows, int K, int M) {
    __shared__ float As[16][64];
    __shared__ float Bs[16][64];

    const int tid = threadIdx.x;          // 0..255
    const int ty = tid >> 4;              // 0..15
    const int tx = tid & 15;              // 0..15
    const int rowBase = blockIdx.y * 64;
    const int colBase = blockIdx.x * 64;

    // A tile load mapping: 64 rows x 16 k -> one float4 per thread
    const int aRow = tid >> 2;            // 0..63
    const int aK4  = (tid & 3) * 4;       // 0,4,8,12
    // B tile load mapping: 16 k x 64 cols -> one float4 per thread
    const int bRow = tid >> 4;            // 0..15
    const int bCol = (tid & 15) * 4;      // 0..60

    float acc[4][4] = {};

    const int gr_a = rowBase + aRow;
    const bool aValid = (gr_a < nrows);
    const float* aPtr = A + (size_t)gr_a * K + aK4;

    for (int k0 = 0; k0 < K; k0 += 16) {
        float4 av = make_float4(0.f, 0.f, 0.f, 0.f);
        if (aValid) av = *(const float4*)(aPtr + k0);
        As[aK4 + 0][aRow] = av.x;
        As[aK4 + 1][aRow] = av.y;
        As[aK4 + 2][aRow] = av.z;
        As[aK4 + 3][aRow] = av.w;

        float4 bv = *(const float4*)&B[(size_t)(k0 + bRow) * M + colBase + bCol];
        *(float4*)&Bs[bRow][bCol] = bv;

        __syncthreads();

        #pragma unroll
        for (int k = 0; k < 16; k++) {
            float ra[4], rb[4];
            #pragma unroll
            for (int i = 0; i < 4; i++) ra[i] = As[k][ty * 4 + i];
            #pragma unroll
            for (int j = 0; j < 4; j++) rb[j] = Bs[k][tx * 4 + j];
            #pragma unroll
            for (int i = 0; i < 4; i++)
                #pragma unroll
                for (int j = 0; j < 4; j++)
                    acc[i][j] += ra[i] * rb[j];
        }
        __syncthreads();
    }

    #pragma unroll
    for (int i = 0; i < 4; i++) {
        int gr = rowBase + ty * 4 + i;
        if (gr < nrows) {
            *(float4*)&C[(size_t)gr * M + colBase + tx * 4] =
                make_float4(acc[i][0], acc[i][1], acc[i][2], acc[i][3]);
        }
    }
}

// ---------------- fused dual SpMM (support + gate) with vectorized atomics ------
// One thread handles 4 channels of one edge. DSHIFT = log2(D/4).
template <int D, int DSHIFT>
__global__ void spmm_dual(const int* __restrict__ rows, const int* __restrict__ cols,
                          const float* __restrict__ vals,
                          const float* __restrict__ sup, const float* __restrict__ gat,
                          float* __restrict__ out, float* __restrict__ gagg) {
    long long t = (long long)blockIdx.x * blockDim.x + threadIdx.x;
    int e = (int)(t >> DSHIFT);
    int c = ((int)t & ((1 << DSHIFT) - 1)) << 2;
    if (e >= E_EDGES) return;

    int r  = __ldg(&rows[e]);
    int cl = __ldg(&cols[e]);
    float v = __ldg(&vals[e]);

    float4 s = *(const float4*)&sup[(size_t)cl * D + c];
    float4 g = *(const float4*)&gat[(size_t)cl * D + c];

    float* po = out  + (size_t)r * D + c;
    float* pg = gagg + (size_t)r * D + c;

    asm volatile("red.global.add.v4.f32 [%0], {%1,%2,%3,%4};"
                 :: "l"(po), "f"(v * s.x), "f"(v * s.y), "f"(v * s.z), "f"(v * s.w)
                 : "memory");
    asm volatile("red.global.add.v4.f32 [%0], {%1,%2,%3,%4};"
                 :: "l"(pg), "f"(v * g.x), "f"(v * g.y), "f"(v * g.z), "f"(v * g.w)
                 : "memory");
}

// ---------------- epilogues ----------------
__global__ void epilogue_relu(const float* __restrict__ gagg, const float* __restrict__ out,
                              float* __restrict__ h, int n) {
    int i = blockIdx.x * blockDim.x + threadIdx.x;
    if (i < n) {
        float s = 1.f / (1.f + expf(-gagg[i]));
        float v = s * out[i];
        h[i] = v > 0.f ? v : 0.f;
    }
}

__global__ void epilogue_final(const float* __restrict__ gagg, float* __restrict__ out, int n) {
    int i = blockIdx.x * blockDim.x + threadIdx.x;
    if (i < n) {
        float s = 1.f / (1.f + expf(-gagg[i]));
        out[i] = s * out[i];
    }
}

// ---------------- launch ----------------
extern "C" void kernel_launch(void* const* d_in, const int* in_sizes, int n_in,
                              void* d_out, int out_size) {
    const float* x    = (const float*)d_in[0];
    const int*   rows = (const int*)  d_in[1];
    const int*   cols = (const int*)  d_in[2];
    const float* vals = (const float*)d_in[3];
    const float* W1   = (const float*)d_in[4];
    const float* G1   = (const float*)d_in[5];
    const float* W2   = (const float*)d_in[6];
    const float* G2   = (const float*)d_in[7];
    float* out2 = (float*)d_out;   // layer-2 support accumulator lives in d_out

    float *p_sup1, *p_gat1, *p_out1, *p_gagg1, *p_h, *p_sup2, *p_gat2, *p_gagg2;
    cudaGetSymbolAddress((void**)&p_sup1,  g_support1);
    cudaGetSymbolAddress((void**)&p_gat1,  g_gate1);
    cudaGetSymbolAddress((void**)&p_out1,  g_out1);
    cudaGetSymbolAddress((void**)&p_gagg1, g_gagg1);
    cudaGetSymbolAddress((void**)&p_h,     g_h);
    cudaGetSymbolAddress((void**)&p_sup2,  g_support2);
    cudaGetSymbolAddress((void**)&p_gat2,  g_gate2);
    cudaGetSymbolAddress((void**)&p_gagg2, g_gagg2);

    const int n1 = N_NODES * D_HID;    // 12.8M
    const int n2 = N_NODES * D_OUT_;   // 6.4M

    // Zero accumulators (out1, gagg1, gagg2, d_out)
    {
        int n4 = n1 / 4;
        int blocks = (n4 + 255) / 256;
        zero_kernel<<<blocks, 256>>>(p_out1, n4);
        zero_kernel<<<blocks, 256>>>(p_gagg1, n4);
        int n4b = n2 / 4;
        int blocksb = (n4b + 255) / 256;
        zero_kernel<<<blocksb, 256>>>(p_gagg2, n4b);
        zero_kernel<<<blocksb, 256>>>(out2, n4b);
    }

    const int gy = (N_NODES + 63) / 64;   // 782

    // Layer 1 GEMMs: support1 = x@W1, gate1 = x@G1   [50000,256]x[256,256]
    {
        dim3 grid(D_HID / 64, gy);
        sgemm64<<<grid, 256>>>(x, W1, p_sup1, N_NODES, D_IN, D_HID);
        sgemm64<<<grid, 256>>>(x, G1, p_gat1, N_NODES, D_IN, D_HID);
    }

    // Layer 1 SpMM (fused support+gate)
    {
        long long threads = (long long)E_EDGES * (D_HID / 4);
        int blocks = (int)((threads + 255) / 256);
        spmm_dual<D_HID, 6><<<blocks, 256>>>(rows, cols, vals, p_sup1, p_gat1,
                                             p_out1, p_gagg1);
    }

    // h = relu(sigmoid(gagg1) * out1)
    epilogue_relu<<<(n1 + 255) / 256, 256>>>(p_gagg1, p_out1, p_h, n1);

    // Layer 2 GEMMs: support2 = h@W2, gate2 = h@G2   [50000,256]x[256,128]
    {
        dim3 grid(D_OUT_ / 64, gy);
        sgemm64<<<grid, 256>>>(p_h, W2, p_sup2, N_NODES, D_HID, D_OUT_);
        sgemm64<<<grid, 256>>>(p_h, G2, p_gat2, N_NODES, D_HID, D_OUT_);
    }

    // Layer 2 SpMM into d_out (support agg) + gagg2
    {
        long long threads = (long long)E_EDGES * (D_OUT_ / 4);
        int blocks = (int)((threads + 255) / 256);
        spmm_dual<D_OUT_, 5><<<blocks, 256>>>(rows, cols, vals, p_sup2, p_gat2,
                                              out2, p_gagg2);
    }

    // logits = sigmoid(gagg2) * d_out   (in place)
    epilogue_final<<<(n2 + 255) / 256, 256>>>(p_gagg2, out2, n2);
}

// round 2
// speedup vs baseline: 1.6130x; 1.6130x over previous
#include <cuda_runtime.h>
#include <math.h>

#define N_NODES 50000
#define E_EDGES 800000
#define D_IN    256
#define D_HID   256
#define D_OUT_  128

// ---------------- device scratch ----------------
__device__ float g_support1[N_NODES * D_HID];
__device__ float g_gate1   [N_NODES * D_HID];
__device__ float g_h       [N_NODES * D_HID];
__device__ float g_support2[N_NODES * D_OUT_];
__device__ float g_gate2   [N_NODES * D_OUT_];
// CSR scratch
__device__ int  g_cnt[N_NODES];
__device__ int  g_cur[N_NODES];
__device__ int  g_rowptr[N_NODES + 1];
__device__ int2 g_epack[E_EDGES];   // {col, val bits} sorted by row

// ---------------- CSR build ----------------
__global__ void zero_counters(int* __restrict__ cnt, int* __restrict__ cur) {
    int i = blockIdx.x * blockDim.x + threadIdx.x;
    if (i < N_NODES) { cnt[i] = 0; cur[i] = 0; }
}

__global__ void hist_kernel(const int* __restrict__ rows, int* __restrict__ cnt) {
    int e = blockIdx.x * blockDim.x + threadIdx.x;
    if (e < E_EDGES) atomicAdd(&cnt[rows[e]], 1);
}

// single-block exclusive scan of cnt[N] -> rowptr[N+1]
__global__ void scan_kernel(const int* __restrict__ cnt, int* __restrict__ rowptr) {
    __shared__ int ssum[1024];
    const int tid = threadIdx.x;
    const int CH = (N_NODES + 1023) / 1024;   // 49
    int base = tid * CH;
    int s = 0;
    for (int i = 0; i < CH; i++) {
        int idx = base + i;
        if (idx < N_NODES) s += cnt[idx];
    }
    ssum[tid] = s;
    __syncthreads();
    // Hillis-Steele inclusive scan
    for (int off = 1; off < 1024; off <<= 1) {
        int v = 0;
        if (tid >= off) v = ssum[tid - off];
        __syncthreads();
        ssum[tid] += v;
        __syncthreads();
    }
    int prefix = (tid == 0) ? 0 : ssum[tid - 1];
    for (int i = 0; i < CH; i++) {
        int idx = base + i;
        if (idx < N_NODES) { rowptr[idx] = prefix; prefix += cnt[idx]; }
    }
    if (tid == 1023) rowptr[N_NODES] = prefix;
}

__global__ void scatter_kernel(const int* __restrict__ rows, const int* __restrict__ cols,
                               const float* __restrict__ vals,
                               const int* __restrict__ rowptr, int* __restrict__ cur,
                               int2* __restrict__ ep) {
    int e = blockIdx.x * blockDim.x + threadIdx.x;
    if (e < E_EDGES) {
        int r = rows[e];
        int pos = rowptr[r] + atomicAdd(&cur[r], 1);
        ep[pos] = make_int2(cols[e], __float_as_int(vals[e]));
    }
}

// ---------------- SGEMM 128x64, BK=16, 8x4 per thread ----------------
__global__ __launch_bounds__(256)
void sgemm128(const float* __restrict__ A, const float* __restrict__ B,
              float* __restrict__ C, int nrows, int K, int M) {
    __shared__ float As[16][128];
    __shared__ float Bs[16][64];

    const int tid = threadIdx.x;
    const int ty = tid >> 4;              // 0..15 -> rows ty*8..+7
    const int tx = tid & 15;              // 0..15 -> cols tx*4..+3
    const int rowBase = blockIdx.y * 128;
    const int colBase = blockIdx.x * 64;

    const int aRow = tid >> 1;            // 0..127
    const int aK   = (tid & 1) * 8;       // 0 or 8
    const int bRow = tid >> 4;            // 0..15
    const int bCol = (tid & 15) * 4;

    float acc[8][4] = {};

    const int gr_a = rowBase + aRow;
    const bool aValid = (gr_a < nrows);
    const float* aPtr = A + (size_t)gr_a * K + aK;

    for (int k0 = 0; k0 < K; k0 += 16) {
        float4 a0 = make_float4(0.f,0.f,0.f,0.f), a1 = a0;
        if (aValid) {
            a0 = *(const float4*)(aPtr + k0);
            a1 = *(const float4*)(aPtr + k0 + 4);
        }
        As[aK + 0][aRow] = a0.x; As[aK + 1][aRow] = a0.y;
        As[aK + 2][aRow] = a0.z; As[aK + 3][aRow] = a0.w;
        As[aK + 4][aRow] = a1.x; As[aK + 5][aRow] = a1.y;
        As[aK + 6][aRow] = a1.z; As[aK + 7][aRow] = a1.w;

        float4 bv = *(const float4*)&B[(size_t)(k0 + bRow) * M + colBase + bCol];
        *(float4*)&Bs[bRow][bCol] = bv;

        __syncthreads();

        #pragma unroll
        for (int k = 0; k < 16; k++) {
            float4 ra0 = *(const float4*)&As[k][ty * 8];
            float4 ra1 = *(const float4*)&As[k][ty * 8 + 4];
            float4 rb  = *(const float4*)&Bs[k][tx * 4];
            float ra[8] = {ra0.x, ra0.y, ra0.z, ra0.w, ra1.x, ra1.y, ra1.z, ra1.w};
            float rbv[4] = {rb.x, rb.y, rb.z, rb.w};
            #pragma unroll
            for (int i = 0; i < 8; i++)
                #pragma unroll
                for (int j = 0; j < 4; j++)
                    acc[i][j] = fmaf(ra[i], rbv[j], acc[i][j]);
        }
        __syncthreads();
    }

    #pragma unroll
    for (int i = 0; i < 8; i++) {
        int gr = rowBase + ty * 8 + i;
        if (gr < nrows) {
            *(float4*)&C[(size_t)gr * M + colBase + tx * 4] =
                make_float4(acc[i][0], acc[i][1], acc[i][2], acc[i][3]);
        }
    }
}

// ---------------- CSR SpMM consumer with fused gating epilogue ----------------
// D channels; D/4 threads per row; 256-thread blocks.
template <int D, bool RELU>
__global__ __launch_bounds__(256)
void spmm_csr(const int* __restrict__ rowptr, const int2* __restrict__ ep,
              const float* __restrict__ sup, const float* __restrict__ gat,
              float* __restrict__ outp) {
    const int TPR = D / 4;
    const int RPB = 256 / TPR;
    const int lane = threadIdx.x & (TPR - 1);
    const int row = blockIdx.x * RPB + threadIdx.x / TPR;
    if (row >= N_NODES) return;
    const int c = lane * 4;

    int e    = __ldg(&rowptr[row]);
    int eend = __ldg(&rowptr[row + 1]);

    float4 as = make_float4(0.f,0.f,0.f,0.f);
    float4 ag = as;

    for (; e < eend; e++) {
        int2 ev = __ldg(&ep[e]);
        float v = __int_as_float(ev.y);
        const float4 sv = *(const float4*)&sup[(size_t)ev.x * D + c];
        const float4 gv = *(const float4*)&gat[(size_t)ev.x * D + c];
        as.x = fmaf(v, sv.x, as.x); as.y = fmaf(v, sv.y, as.y);
        as.z = fmaf(v, sv.z, as.z); as.w = fmaf(v, sv.w, as.w);
        ag.x = fmaf(v, gv.x, ag.x); ag.y = fmaf(v, gv.y, ag.y);
        ag.z = fmaf(v, gv.z, ag.z); ag.w = fmaf(v, gv.w, ag.w);
    }

    float4 o;
    o.x = as.x / (1.f + expf(-ag.x));
    o.y = as.y / (1.f + expf(-ag.y));
    o.z = as.z / (1.f + expf(-ag.z));
    o.w = as.w / (1.f + expf(-ag.w));
    if (RELU) {
        o.x = fmaxf(o.x, 0.f); o.y = fmaxf(o.y, 0.f);
        o.z = fmaxf(o.z, 0.f); o.w = fmaxf(o.w, 0.f);
    }
    *(float4*)&outp[(size_t)row * D + c] = o;
}

// ---------------- launch ----------------
extern "C" void kernel_launch(void* const* d_in, const int* in_sizes, int n_in,
                              void* d_out, int out_size) {
    const float* x    = (const float*)d_in[0];
    const int*   rows = (const int*)  d_in[1];
    const int*   cols = (const int*)  d_in[2];
    const float* vals = (const float*)d_in[3];
    const float* W1   = (const float*)d_in[4];
    const float* G1   = (const float*)d_in[5];
    const float* W2   = (const float*)d_in[6];
    const float* G2   = (const float*)d_in[7];
    float* out2 = (float*)d_out;

    float *p_sup1, *p_gat1, *p_h, *p_sup2, *p_gat2;
    int *p_cnt, *p_cur, *p_rowptr;
    int2* p_ep;
    cudaGetSymbolAddress((void**)&p_sup1,  g_support1);
    cudaGetSymbolAddress((void**)&p_gat1,  g_gate1);
    cudaGetSymbolAddress((void**)&p_h,     g_h);
    cudaGetSymbolAddress((void**)&p_sup2,  g_support2);
    cudaGetSymbolAddress((void**)&p_gat2,  g_gate2);
    cudaGetSymbolAddress((void**)&p_cnt,   g_cnt);
    cudaGetSymbolAddress((void**)&p_cur,   g_cur);
    cudaGetSymbolAddress((void**)&p_rowptr,g_rowptr);
    cudaGetSymbolAddress((void**)&p_ep,    g_epack);

    // --- CSR build ---
    zero_counters<<<(N_NODES + 255) / 256, 256>>>(p_cnt, p_cur);
    hist_kernel<<<(E_EDGES + 255) / 256, 256>>>(rows, p_cnt);
    scan_kernel<<<1, 1024>>>(p_cnt, p_rowptr);
    scatter_kernel<<<(E_EDGES + 255) / 256, 256>>>(rows, cols, vals, p_rowptr, p_cur, p_ep);

    const int gy = (N_NODES + 127) / 128;  // 391

    // --- Layer 1 GEMMs ---
    {
        dim3 grid(D_HID / 64, gy);
        sgemm128<<<grid, 256>>>(x, W1, p_sup1, N_NODES, D_IN, D_HID);
        sgemm128<<<grid, 256>>>(x, G1, p_gat1, N_NODES, D_IN, D_HID);
    }

    // --- Layer 1 SpMM + gate + relu -> h ---
    {
        int rpb = 256 / (D_HID / 4);  // 4 rows per block
        int grid = (N_NODES + rpb - 1) / rpb;
        spmm_csr<D_HID, true><<<grid, 256>>>(p_rowptr, p_ep, p_sup1, p_gat1, p_h);
    }

    // --- Layer 2 GEMMs ---
    {
        dim3 grid(D_OUT_ / 64, gy);
        sgemm128<<<grid, 256>>>(p_h, W2, p_sup2, N_NODES, D_HID, D_OUT_);
        sgemm128<<<grid, 256>>>(p_h, G2, p_gat2, N_NODES, D_HID, D_OUT_);
    }

    // --- Layer 2 SpMM + gate -> d_out ---
    {
        int rpb = 256 / (D_OUT_ / 4);  // 8 rows per block
        int grid = (N_NODES + rpb - 1) / rpb;
        spmm_csr<D_OUT_, false><<<grid, 256>>>(p_rowptr, p_ep, p_sup2, p_gat2, out2);
    }
}

// round 4
// speedup vs baseline: 2.2872x; 1.4180x over previous
#include <cuda_runtime.h>
#include <cuda_bf16.h>
#include <math.h>
#include <stdint.h>

#define N_NODES 50000
#define E_EDGES 800000
#define D_IN    256
#define D_HID   256
#define D_OUT_  128

// ---------------- device scratch ----------------
__device__ float g_sup1[N_NODES * D_HID];
__device__ float g_gat1[N_NODES * D_HID];
__device__ float g_sup2[N_NODES * D_OUT_];
__device__ float g_gat2[N_NODES * D_OUT_];
__device__ __nv_bfloat16 g_xh[N_NODES * D_IN];
__device__ __nv_bfloat16 g_xl[N_NODES * D_IN];
__device__ __nv_bfloat16 g_hh[N_NODES * D_HID];
__device__ __nv_bfloat16 g_hl[N_NODES * D_HID];
// weights transposed to [n][k], hi/lo split
__device__ __nv_bfloat16 g_w1h[D_HID * D_IN], g_w1l[D_HID * D_IN];
__device__ __nv_bfloat16 g_g1h[D_HID * D_IN], g_g1l[D_HID * D_IN];
__device__ __nv_bfloat16 g_w2h[D_OUT_ * D_HID], g_w2l[D_OUT_ * D_HID];
__device__ __nv_bfloat16 g_g2h[D_OUT_ * D_HID], g_g2l[D_OUT_ * D_HID];
// CSR scratch
__device__ int  g_cnt[N_NODES];
__device__ int  g_cur[N_NODES];
__device__ int  g_rowptr[N_NODES + 1];
__device__ int2 g_epack[E_EDGES];

// ---------------- PTX helpers (all arch-portable: sm_80+) ----------------
__device__ __forceinline__ uint32_t smem_u32(const void* p) {
    uint32_t a;
    asm("{ .reg .u64 t; cvta.to.shared.u64 t, %1; cvt.u32.u64 %0, t; }" : "=r"(a) : "l"(p));
    return a;
}
__device__ __forceinline__ void cp16(uint32_t dst, const void* src, uint32_t sz) {
    asm volatile("cp.async.cg.shared.global [%0], [%1], 16, %2;"
                 :: "r"(dst), "l"(src), "r"(sz) : "memory");
}
#define CP_COMMIT() asm volatile("cp.async.commit_group;" ::: "memory")
#define CP_WAIT0()  asm volatile("cp.async.wait_group 0;" ::: "memory")
#define LDSM4(r, addr) \
    asm volatile("ldmatrix.sync.aligned.m8n8.x4.shared.b16 {%0,%1,%2,%3}, [%4];" \
                 : "=r"((r)[0]), "=r"((r)[1]), "=r"((r)[2]), "=r"((r)[3]) : "r"(addr))
#define MMA16816(d, a, b) \
    asm volatile("mma.sync.aligned.m16n8k16.row.col.f32.bf16.bf16.f32 " \
                 "{%0,%1,%2,%3}, {%4,%5,%6,%7}, {%8,%9}, {%0,%1,%2,%3};" \
                 : "+f"((d)[0]), "+f"((d)[1]), "+f"((d)[2]), "+f"((d)[3]) \
                 : "r"((a)[0]), "r"((a)[1]), "r"((a)[2]), "r"((a)[3]), \
                   "r"((b)[0]), "r"((b)[1]))

// ---------------- CSR build ----------------
__global__ void zero_counters(int* __restrict__ cnt, int* __restrict__ cur) {
    int i = blockIdx.x * blockDim.x + threadIdx.x;
    if (i < N_NODES) { cnt[i] = 0; cur[i] = 0; }
}
__global__ void hist_kernel(const int* __restrict__ rows, int* __restrict__ cnt) {
    int e = blockIdx.x * blockDim.x + threadIdx.x;
    if (e < E_EDGES) atomicAdd(&cnt[rows[e]], 1);
}
__global__ void scan_kernel(const int* __restrict__ cnt, int* __restrict__ rowptr) {
    __shared__ int ssum[1024];
    const int tid = threadIdx.x;
    const int CH = (N_NODES + 1023) / 1024;
    int base = tid * CH;
    int s = 0;
    for (int i = 0; i < CH; i++) { int idx = base + i; if (idx < N_NODES) s += cnt[idx]; }
    ssum[tid] = s;
    __syncthreads();
    for (int off = 1; off < 1024; off <<= 1) {
        int v = 0;
        if (tid >= off) v = ssum[tid - off];
        __syncthreads();
        ssum[tid] += v;
        __syncthreads();
    }
    int prefix = (tid == 0) ? 0 : ssum[tid - 1];
    for (int i = 0; i < CH; i++) {
        int idx = base + i;
        if (idx < N_NODES) { rowptr[idx] = prefix; prefix += cnt[idx]; }
    }
    if (tid == 1023) rowptr[N_NODES] = prefix;
}
__global__ void scatter_kernel(const int* __restrict__ rows, const int* __restrict__ cols,
                               const float* __restrict__ vals,
                               const int* __restrict__ rowptr, int* __restrict__ cur,
                               int2* __restrict__ ep) {
    int e = blockIdx.x * blockDim.x + threadIdx.x;
    if (e < E_EDGES) {
        int r = rows[e];
        int pos = rowptr[r] + atomicAdd(&cur[r], 1);
        ep[pos] = make_int2(cols[e], __float_as_int(vals[e]));
    }
}

// ---------------- fp32 -> bf16 hi/lo split ----------------
__global__ void split_kernel(const float* __restrict__ in, __nv_bfloat16* __restrict__ oh,
                             __nv_bfloat16* __restrict__ ol, int n) {
    int i = blockIdx.x * blockDim.x + threadIdx.x;
    if (i < n) {
        float v = in[i];
        __nv_bfloat16 h = __float2bfloat16(v);
        oh[i] = h;
        ol[i] = __float2bfloat16(v - __bfloat162float(h));
    }
}
__global__ void split_w_kernel(const float* __restrict__ in, __nv_bfloat16* __restrict__ oh,
                               __nv_bfloat16* __restrict__ ol, int K, int M) {
    int i = blockIdx.x * blockDim.x + threadIdx.x;
    if (i < K * M) {
        int n = i / K, k = i % K;
        float v = in[(size_t)k * M + n];
        __nv_bfloat16 h = __float2bfloat16(v);
        oh[i] = h;
        ol[i] = __float2bfloat16(v - __bfloat162float(h));
    }
}

// ---------------- mma.sync GEMM: C[nrows,ldc block] = A[nrows,256] * B^T ----------------
// Block tile 128x128, warp tile 64x32 (8 warps: 2M x 4N), K chunk 32, 2-stage cp.async.
// 3 split terms accumulated into one fp32 accumulator: AhBh + AlBh + AhBl.
// SMEM rows padded to 80B (32 bf16 data + 8 pad) -> conflict-free ldmatrix.
#define STAGE_B 40960   // 4 matrices * 128 rows * 80 B

__global__ void __launch_bounds__(256)
gemm_mma(const __nv_bfloat16* __restrict__ Ah, const __nv_bfloat16* __restrict__ Al,
         const __nv_bfloat16* __restrict__ Bh, const __nv_bfloat16* __restrict__ Bl,
         float* __restrict__ C, int nrows, int ldc) {
    extern __shared__ __align__(128) char smem[];
    const int tid  = threadIdx.x;
    const int lane = tid & 31;
    const int wid  = tid >> 5;
    const int mwarp = wid & 1;
    const int nwarp = wid >> 1;
    const int rowBase = blockIdx.x * 128;
    const int colBase = blockIdx.y * 128;
    const uint32_t sb = smem_u32(smem);

    float acc[4][4][4] = {};

    auto load_stage = [&](int s, int k0) {
        uint32_t base = sb + s * STAGE_B;
        int r = tid >> 2;          // 0..63
        int c = tid & 3;           // 16B chunk
        #pragma unroll
        for (int half = 0; half < 2; half++) {
            int row = r + half * 64;
            uint32_t ro = row * 80 + c * 16;
            int gr = rowBase + row;
            uint32_t sz = (gr < nrows) ? 16u : 0u;
            size_t aoff = (size_t)gr * 256 + k0 + c * 8;
            cp16(base + ro,          Ah + aoff, sz);
            cp16(base + 10240 + ro,  Al + aoff, sz);
            int gn = colBase + row;
            size_t boff = (size_t)gn * 256 + k0 + c * 8;
            cp16(base + 20480 + ro,  Bh + boff, 16);
            cp16(base + 30720 + ro,  Bl + boff, 16);
        }
        CP_COMMIT();
    };

    auto do_mma = [&](uint32_t (&a)[16], uint32_t (&b)[8]) {
        #pragma unroll
        for (int mt = 0; mt < 4; mt++)
            #pragma unroll
            for (int nt = 0; nt < 4; nt++)
                MMA16816(acc[mt][nt], &a[mt * 4], &b[(nt >> 1) * 4 + (nt & 1) * 2]);
    };

    load_stage(0, 0);

    for (int ch = 0; ch < 8; ch++) {
        CP_WAIT0();
        __syncthreads();
        if (ch < 7) load_stage((ch + 1) & 1, (ch + 1) * 32);

        uint32_t base = sb + (ch & 1) * STAGE_B;
        #pragma unroll
        for (int j = 0; j < 2; j++) {
            uint32_t ah[16], al[16], bb[8];
            uint32_t arow = mwarp * 64 + (lane & 15);
            uint32_t achk = j * 2 + (lane >> 4);
            uint32_t aoffb = arow * 80 + achk * 16;
            uint32_t brow = nwarp * 32 + (lane & 7) + ((lane >> 4) << 3);
            uint32_t bchk = j * 2 + ((lane >> 3) & 1);
            uint32_t boffb = brow * 80 + bchk * 16;

            #pragma unroll
            for (int mt = 0; mt < 4; mt++)
                LDSM4(&ah[mt * 4], base + aoffb + mt * 16 * 80);
            #pragma unroll
            for (int p = 0; p < 2; p++)
                LDSM4(&bb[p * 4], base + 20480 + boffb + p * 16 * 80);
            do_mma(ah, bb);                        // Ah * Bh
            #pragma unroll
            for (int mt = 0; mt < 4; mt++)
                LDSM4(&al[mt * 4], base + 10240 + aoffb + mt * 16 * 80);
            do_mma(al, bb);                        // Al * Bh
            #pragma unroll
            for (int p = 0; p < 2; p++)
                LDSM4(&bb[p * 4], base + 30720 + boffb + p * 16 * 80);
            do_mma(ah, bb);                        // Ah * Bl
        }
        __syncthreads();
    }

    // epilogue: direct global stores
    #pragma unroll
    for (int mt = 0; mt < 4; mt++) {
        int r0 = rowBase + mwarp * 64 + mt * 16 + (lane >> 2);
        #pragma unroll
        for (int half = 0; half < 2; half++) {
            int r = r0 + half * 8;
            if (r < nrows) {
                float* cp = C + (size_t)r * ldc + colBase + nwarp * 32 + (lane & 3) * 2;
                #pragma unroll
                for (int nt = 0; nt < 4; nt++)
                    *(float2*)(cp + nt * 8) =
                        make_float2(acc[mt][nt][half * 2], acc[mt][nt][half * 2 + 1]);
            }
        }
    }
}

// ---------------- CSR SpMM consumers ----------------
__global__ void __launch_bounds__(256)
spmm_l1(const int* __restrict__ rowptr, const int2* __restrict__ ep,
        const float* __restrict__ sup, const float* __restrict__ gat,
        __nv_bfloat16* __restrict__ hh, __nv_bfloat16* __restrict__ hl) {
    const int TPR = 64;
    const int lane = threadIdx.x & (TPR - 1);
    const int row = blockIdx.x * 4 + threadIdx.x / TPR;
    if (row >= N_NODES) return;
    const int c = lane * 4;

    int e = __ldg(&rowptr[row]);
    int eend = __ldg(&rowptr[row + 1]);
    float4 as = make_float4(0.f, 0.f, 0.f, 0.f), ag = as;
    for (; e < eend; e++) {
        int2 ev = __ldg(&ep[e]);
        float v = __int_as_float(ev.y);
        const float4 sv = *(const float4*)&sup[(size_t)ev.x * 256 + c];
        const float4 gv = *(const float4*)&gat[(size_t)ev.x * 256 + c];
        as.x = fmaf(v, sv.x, as.x); as.y = fmaf(v, sv.y, as.y);
        as.z = fmaf(v, sv.z, as.z); as.w = fmaf(v, sv.w, as.w);
        ag.x = fmaf(v, gv.x, ag.x); ag.y = fmaf(v, gv.y, ag.y);
        ag.z = fmaf(v, gv.z, ag.z); ag.w = fmaf(v, gv.w, ag.w);
    }
    float o[4];
    o[0] = fmaxf(as.x / (1.f + expf(-ag.x)), 0.f);
    o[1] = fmaxf(as.y / (1.f + expf(-ag.y)), 0.f);
    o[2] = fmaxf(as.z / (1.f + expf(-ag.z)), 0.f);
    o[3] = fmaxf(as.w / (1.f + expf(-ag.w)), 0.f);
    __nv_bfloat16 h[4], l[4];
    #pragma unroll
    for (int j = 0; j < 4; j++) {
        h[j] = __float2bfloat16(o[j]);
        l[j] = __float2bfloat16(o[j] - __bfloat162float(h[j]));
    }
    *(uint2*)&hh[(size_t)row * 256 + c] = *(uint2*)h;
    *(uint2*)&hl[(size_t)row * 256 + c] = *(uint2*)l;
}
__global__ void __launch_bounds__(256)
spmm_l2(const int* __restrict__ rowptr, const int2* __restrict__ ep,
        const float* __restrict__ sup, const float* __restrict__ gat,
        float* __restrict__ outp) {
    const int TPR = 32;
    const int lane = threadIdx.x & (TPR - 1);
    const int row = blockIdx.x * 8 + threadIdx.x / TPR;
    if (row >= N_NODES) return;
    const int c = lane * 4;

    int e = __ldg(&rowptr[row]);
    int eend = __ldg(&rowptr[row + 1]);
    float4 as = make_float4(0.f, 0.f, 0.f, 0.f), ag = as;
    for (; e < eend; e++) {
        int2 ev = __ldg(&ep[e]);
        float v = __int_as_float(ev.y);
        const float4 sv = *(const float4*)&sup[(size_t)ev.x * 128 + c];
        const float4 gv = *(const float4*)&gat[(size_t)ev.x * 128 + c];
        as.x = fmaf(v, sv.x, as.x); as.y = fmaf(v, sv.y, as.y);
        as.z = fmaf(v, sv.z, as.z); as.w = fmaf(v, sv.w, as.w);
        ag.x = fmaf(v, gv.x, ag.x); ag.y = fmaf(v, gv.y, ag.y);
        ag.z = fmaf(v, gv.z, ag.z); ag.w = fmaf(v, gv.w, ag.w);
    }
    float4 o;
    o.x = as.x / (1.f + expf(-ag.x));
    o.y = as.y / (1.f + expf(-ag.y));
    o.z = as.z / (1.f + expf(-ag.z));
    o.w = as.w / (1.f + expf(-ag.w));
    *(float4*)&outp[(size_t)row * 128 + c] = o;
}

// ---------------- launch ----------------
extern "C" void kernel_launch(void* const* d_in, const int* in_sizes, int n_in,
                              void* d_out, int out_size) {
    const float* x    = (const float*)d_in[0];
    const int*   rows = (const int*)  d_in[1];
    const int*   cols = (const int*)  d_in[2];
    const float* vals = (const float*)d_in[3];
    const float* W1   = (const float*)d_in[4];
    const float* G1   = (const float*)d_in[5];
    const float* W2   = (const float*)d_in[6];
    const float* G2   = (const float*)d_in[7];
    float* out2 = (float*)d_out;

    float *p_sup1, *p_gat1, *p_sup2, *p_gat2;
    __nv_bfloat16 *p_xh, *p_xl, *p_hh, *p_hl;
    __nv_bfloat16 *p_w1h, *p_w1l, *p_g1h, *p_g1l, *p_w2h, *p_w2l, *p_g2h, *p_g2l;
    int *p_cnt, *p_cur, *p_rowptr;
    int2* p_ep;
    cudaGetSymbolAddress((void**)&p_sup1, g_sup1);
    cudaGetSymbolAddress((void**)&p_gat1, g_gat1);
    cudaGetSymbolAddress((void**)&p_sup2, g_sup2);
    cudaGetSymbolAddress((void**)&p_gat2, g_gat2);
    cudaGetSymbolAddress((void**)&p_xh, g_xh);
    cudaGetSymbolAddress((void**)&p_xl, g_xl);
    cudaGetSymbolAddress((void**)&p_hh, g_hh);
    cudaGetSymbolAddress((void**)&p_hl, g_hl);
    cudaGetSymbolAddress((void**)&p_w1h, g_w1h);
    cudaGetSymbolAddress((void**)&p_w1l, g_w1l);
    cudaGetSymbolAddress((void**)&p_g1h, g_g1h);
    cudaGetSymbolAddress((void**)&p_g1l, g_g1l);
    cudaGetSymbolAddress((void**)&p_w2h, g_w2h);
    cudaGetSymbolAddress((void**)&p_w2l, g_w2l);
    cudaGetSymbolAddress((void**)&p_g2h, g_g2h);
    cudaGetSymbolAddress((void**)&p_g2l, g_g2l);
    cudaGetSymbolAddress((void**)&p_cnt, g_cnt);
    cudaGetSymbolAddress((void**)&p_cur, g_cur);
    cudaGetSymbolAddress((void**)&p_rowptr, g_rowptr);
    cudaGetSymbolAddress((void**)&p_ep, g_epack);

    cudaFuncSetAttribute(gemm_mma, cudaFuncAttributeMaxDynamicSharedMemorySize, 2 * STAGE_B);

    // --- CSR build ---
    zero_counters<<<(N_NODES + 255) / 256, 256>>>(p_cnt, p_cur);
    hist_kernel<<<(E_EDGES + 255) / 256, 256>>>(rows, p_cnt);
    scan_kernel<<<1, 1024>>>(p_cnt, p_rowptr);
    scatter_kernel<<<(E_EDGES + 255) / 256, 256>>>(rows, cols, vals, p_rowptr, p_cur, p_ep);

    // --- conversions ---
    split_kernel<<<(N_NODES * D_IN + 255) / 256, 256>>>(x, p_xh, p_xl, N_NODES * D_IN);
    split_w_kernel<<<(D_IN * D_HID + 255) / 256, 256>>>(W1, p_w1h, p_w1l, D_IN, D_HID);
    split_w_kernel<<<(D_IN * D_HID + 255) / 256, 256>>>(G1, p_g1h, p_g1l, D_IN, D_HID);
    split_w_kernel<<<(D_HID * D_OUT_ + 255) / 256, 256>>>(W2, p_w2h, p_w2l, D_HID, D_OUT_);
    split_w_kernel<<<(D_HID * D_OUT_ + 255) / 256, 256>>>(G2, p_g2h, p_g2l, D_HID, D_OUT_);

    const int rt = (N_NODES + 127) / 128;   // 391

    // --- Layer 1 GEMMs ---
    {
        dim3 grid(rt, 2);
        gemm_mma<<<grid, 256, 2 * STAGE_B>>>(p_xh, p_xl, p_w1h, p_w1l, p_sup1, N_NODES, 256);
        gemm_mma<<<grid, 256, 2 * STAGE_B>>>(p_xh, p_xl, p_g1h, p_g1l, p_gat1, N_NODES, 256);
    }

    // --- Layer 1 SpMM + gate + relu -> split h ---
    spmm_l1<<<(N_NODES + 3) / 4, 256>>>(p_rowptr, p_ep, p_sup1, p_gat1, p_hh, p_hl);

    // --- Layer 2 GEMMs ---
    {
        dim3 grid(rt, 1);
        gemm_mma<<<grid, 256, 2 * STAGE_B>>>(p_hh, p_hl, p_w2h, p_w2l, p_sup2, N_NODES, 128);
        gemm_mma<<<grid, 256, 2 * STAGE_B>>>(p_hh, p_hl, p_g2h, p_g2l, p_gat2, N_NODES, 128);
    }

    // --- Layer 2 SpMM + gate -> d_out ---
    spmm_l2<<<(N_NODES + 7) / 8, 256>>>(p_rowptr, p_ep, p_sup2, p_gat2, out2);
}

// round 5
// speedup vs baseline: 3.0802x; 1.3467x over previous
#include <cuda_runtime.h>
#include <cuda_bf16.h>
#include <math.h>
#include <stdint.h>

#define N_NODES 50000
#define E_EDGES 800000
#define D_IN    256
#define D_HID   256
#define D_OUT_  128

// ---------------- device scratch ----------------
__device__ __nv_bfloat16 g_z1h[N_NODES * 256];
__device__ __nv_bfloat16 g_z1l[N_NODES * 256];
__device__ float         g_h  [N_NODES * 256];
__device__ __nv_bfloat16 g_z2h[N_NODES * 256];
__device__ __nv_bfloat16 g_z2l[N_NODES * 256];
// weights transposed to [n][k], hi/lo split
__device__ __nv_bfloat16 g_w1h[D_HID * D_IN], g_w1l[D_HID * D_IN];
__device__ __nv_bfloat16 g_g1h[D_HID * D_IN], g_g1l[D_HID * D_IN];
__device__ __nv_bfloat16 g_w2h[D_OUT_ * D_HID], g_w2l[D_OUT_ * D_HID];
__device__ __nv_bfloat16 g_g2h[D_OUT_ * D_HID], g_g2l[D_OUT_ * D_HID];
// CSR scratch
__device__ int  g_cnt[N_NODES];
__device__ int  g_cur[N_NODES];
__device__ int  g_rowptr[N_NODES + 1];
__device__ int2 g_epack[E_EDGES];

// ---------------- PTX helpers (arch-portable sm_80+) ----------------
__device__ __forceinline__ uint32_t smem_u32(const void* p) {
    uint32_t a;
    asm("{ .reg .u64 t; cvta.to.shared.u64 t, %1; cvt.u32.u64 %0, t; }" : "=r"(a) : "l"(p));
    return a;
}
__device__ __forceinline__ void cp16(uint32_t dst, const void* src, uint32_t sz) {
    asm volatile("cp.async.cg.shared.global [%0], [%1], 16, %2;"
                 :: "r"(dst), "l"(src), "r"(sz) : "memory");
}
#define CP_COMMIT() asm volatile("cp.async.commit_group;" ::: "memory")
#define CP_WAIT0()  asm volatile("cp.async.wait_group 0;" ::: "memory")
#define LDSM4(r, addr) \
    asm volatile("ldmatrix.sync.aligned.m8n8.x4.shared.b16 {%0,%1,%2,%3}, [%4];" \
                 : "=r"((r)[0]), "=r"((r)[1]), "=r"((r)[2]), "=r"((r)[3]) : "r"(addr))
#define MMA16816(d, a, b) \
    asm volatile("mma.sync.aligned.m16n8k16.row.col.f32.bf16.bf16.f32 " \
                 "{%0,%1,%2,%3}, {%4,%5,%6,%7}, {%8,%9}, {%0,%1,%2,%3};" \
                 : "+f"((d)[0]), "+f"((d)[1]), "+f"((d)[2]), "+f"((d)[3]) \
                 : "r"((a)[0]), "r"((a)[1]), "r"((a)[2]), "r"((a)[3]), \
                   "r"((b)[0]), "r"((b)[1]))

// ---------------- CSR build ----------------
__global__ void zero_counters(int* __restrict__ cnt, int* __restrict__ cur) {
    int i = blockIdx.x * blockDim.x + threadIdx.x;
    if (i < N_NODES) { cnt[i] = 0; cur[i] = 0; }
}
__global__ void hist_kernel(const int* __restrict__ rows, int* __restrict__ cnt) {
    int e = blockIdx.x * blockDim.x + threadIdx.x;
    if (e < E_EDGES) atomicAdd(&cnt[rows[e]], 1);
}
__global__ void scan_kernel(const int* __restrict__ cnt, int* __restrict__ rowptr) {
    __shared__ int ssum[1024];
    const int tid = threadIdx.x;
    const int CH = (N_NODES + 1023) / 1024;
    int base = tid * CH;
    int s = 0;
    for (int i = 0; i < CH; i++) { int idx = base + i; if (idx < N_NODES) s += cnt[idx]; }
    ssum[tid] = s;
    __syncthreads();
    for (int off = 1; off < 1024; off <<= 1) {
        int v = 0;
        if (tid >= off) v = ssum[tid - off];
        __syncthreads();
        ssum[tid] += v;
        __syncthreads();
    }
    int prefix = (tid == 0) ? 0 : ssum[tid - 1];
    for (int i = 0; i < CH; i++) {
        int idx = base + i;
        if (idx < N_NODES) { rowptr[idx] = prefix; prefix += cnt[idx]; }
    }
    if (tid == 1023) rowptr[N_NODES] = prefix;
}
__global__ void scatter_kernel(const int* __restrict__ rows, const int* __restrict__ cols,
                               const float* __restrict__ vals,
                               const int* __restrict__ rowptr, int* __restrict__ cur,
                               int2* __restrict__ ep) {
    int e = blockIdx.x * blockDim.x + threadIdx.x;
    if (e < E_EDGES) {
        int r = rows[e];
        int pos = rowptr[r] + atomicAdd(&cur[r], 1);
        ep[pos] = make_int2(cols[e], __float_as_int(vals[e]));
    }
}

// ---------------- weight transpose + split ----------------
__global__ void split_w_kernel(const float* __restrict__ in, __nv_bfloat16* __restrict__ oh,
                               __nv_bfloat16* __restrict__ ol, int K, int M) {
    int i = blockIdx.x * blockDim.x + threadIdx.x;
    if (i < K * M) {
        int n = i / K, k = i % K;
        float v = in[(size_t)k * M + n];
        __nv_bfloat16 h = __float2bfloat16(v);
        oh[i] = h;
        ol[i] = __float2bfloat16(v - __bfloat162float(h));
    }
}

// ---------------- SpMM: Z = A * src (D=256), epilogue writes bf16 hi/lo ----
__global__ void __launch_bounds__(256)
spmm_z(const int* __restrict__ rowptr, const int2* __restrict__ ep,
       const float* __restrict__ src,
       __nv_bfloat16* __restrict__ zh, __nv_bfloat16* __restrict__ zl) {
    const int lane = threadIdx.x & 63;
    const int row = blockIdx.x * 4 + (threadIdx.x >> 6);
    if (row >= N_NODES) return;
    const int c = lane * 4;

    int e = __ldg(&rowptr[row]);
    int eend = __ldg(&rowptr[row + 1]);
    float4 as = make_float4(0.f, 0.f, 0.f, 0.f);
    for (; e < eend; e++) {
        int2 ev = __ldg(&ep[e]);
        float v = __int_as_float(ev.y);
        const float4 sv = *(const float4*)&src[(size_t)ev.x * 256 + c];
        as.x = fmaf(v, sv.x, as.x); as.y = fmaf(v, sv.y, as.y);
        as.z = fmaf(v, sv.z, as.z); as.w = fmaf(v, sv.w, as.w);
    }
    float o[4] = {as.x, as.y, as.z, as.w};
    __nv_bfloat16 h[4], l[4];
    #pragma unroll
    for (int j = 0; j < 4; j++) {
        h[j] = __float2bfloat16(o[j]);
        l[j] = __float2bfloat16(o[j] - __bfloat162float(h[j]));
    }
    *(uint2*)&zh[(size_t)row * 256 + c] = *(uint2*)h;
    *(uint2*)&zl[(size_t)row * 256 + c] = *(uint2*)l;
}

// ---------------- fused dual GEMM + gating epilogue ----------------
// Block tile 128(M) x 64(N); 8 warps = 4M x 2N, warp tile 32x32 per matrix.
// Computes S = Z@W^T, G = Z@G^T (3-term bf16 split each), O = sigmoid(G)*S (+relu).
// SMEM per stage: A hi/lo 128x80, 4 B arrays 64x80 = 40960 B; 2 stages.
#define STAGE_B 40960

template <bool RELU>
__global__ void __launch_bounds__(256)
gemm_dual(const __nv_bfloat16* __restrict__ Ah, const __nv_bfloat16* __restrict__ Al,
          const __nv_bfloat16* __restrict__ BWh, const __nv_bfloat16* __restrict__ BWl,
          const __nv_bfloat16* __restrict__ BGh, const __nv_bfloat16* __restrict__ BGl,
          float* __restrict__ O, int nrows, int ldc) {
    extern __shared__ __align__(128) char smem[];
    const int tid  = threadIdx.x;
    const int lane = tid & 31;
    const int wid  = tid >> 5;
    const int mwarp = wid >> 1;            // 0..3
    const int nwarp = wid & 1;             // 0..1
    const int rowBase = blockIdx.x * 128;
    const int colBase = blockIdx.y * 64;
    const uint32_t sb = smem_u32(smem);

    // smem layout within a stage
    const uint32_t AH = 0, AL = 10240, WH = 20480, WL = 25600, GH = 30720, GL = 35840;

    float accW[2][4][4] = {};
    float accG[2][4][4] = {};

    auto load_stage = [&](int s, int k0) {
        uint32_t base = sb + s * STAGE_B;
        int r = tid >> 2;                  // 0..63
        int c = tid & 3;                   // 16B chunk within 64B row
        uint32_t ro = r * 80 + c * 16;
        // A: 128 rows (two halves)
        #pragma unroll
        for (int half = 0; half < 2; half++) {
            int row = r + half * 64;
            uint32_t ro2 = row * 80 + c * 16;
            int gr = rowBase + row;
            uint32_t sz = (gr < nrows) ? 16u : 0u;
            size_t aoff = (size_t)gr * 256 + k0 + c * 8;
            cp16(base + AH + ro2, Ah + aoff, sz);
            cp16(base + AL + ro2, Al + aoff, sz);
        }
        // B: 64 rows x 4 arrays
        {
            int gn = colBase + r;
            size_t boff = (size_t)gn * 256 + k0 + c * 8;
            cp16(base + WH + ro, BWh + boff, 16);
            cp16(base + WL + ro, BWl + boff, 16);
            cp16(base + GH + ro, BGh + boff, 16);
            cp16(base + GL + ro, BGl + boff, 16);
        }
        CP_COMMIT();
    };

    auto do_mma = [&](float (&acc)[2][4][4], uint32_t (&a)[8], uint32_t (&b)[8]) {
        #pragma unroll
        for (int mt = 0; mt < 2; mt++)
            #pragma unroll
            for (int nt = 0; nt < 4; nt++)
                MMA16816(acc[mt][nt], &a[mt * 4], &b[(nt >> 1) * 4 + (nt & 1) * 2]);
    };

    load_stage(0, 0);

    for (int ch = 0; ch < 8; ch++) {
        CP_WAIT0();
        __syncthreads();
        if (ch < 7) load_stage((ch + 1) & 1, (ch + 1) * 32);

        uint32_t base = sb + (ch & 1) * STAGE_B;
        #pragma unroll
        for (int j = 0; j < 2; j++) {
            uint32_t ah[8], al[8], bb[8];
            uint32_t aoffb = (mwarp * 32 + (lane & 15)) * 80 + (j * 2 + (lane >> 4)) * 16;
            uint32_t boffb = (nwarp * 32 + (lane & 7) + ((lane >> 4) << 3)) * 80 +
                             (j * 2 + ((lane >> 3) & 1)) * 16;

            LDSM4(&ah[0], base + AH + aoffb);
            LDSM4(&ah[4], base + AH + aoffb + 16 * 80);
            LDSM4(&bb[0], base + WH + boffb);
            LDSM4(&bb[4], base + WH + boffb + 16 * 80);
            do_mma(accW, ah, bb);                      // Ah*Wh
            LDSM4(&al[0], base + AL + aoffb);
            LDSM4(&al[4], base + AL + aoffb + 16 * 80);
            do_mma(accW, al, bb);                      // Al*Wh
            LDSM4(&bb[0], base + WL + boffb);
            LDSM4(&bb[4], base + WL + boffb + 16 * 80);
            do_mma(accW, ah, bb);                      // Ah*Wl
            LDSM4(&bb[0], base + GH + boffb);
            LDSM4(&bb[4], base + GH + boffb + 16 * 80);
            do_mma(accG, ah, bb);                      // Ah*Gh
            do_mma(accG, al, bb);                      // Al*Gh
            LDSM4(&bb[0], base + GL + boffb);
            LDSM4(&bb[4], base + GL + boffb + 16 * 80);
            do_mma(accG, ah, bb);                      // Ah*Gl
        }
        __syncthreads();
    }

    // epilogue: O = sigmoid(G) * S (+relu)
    #pragma unroll
    for (int mt = 0; mt < 2; mt++) {
        int r0 = rowBase + mwarp * 32 + mt * 16 + (lane >> 2);
        #pragma unroll
        for (int half = 0; half < 2; half++) {
            int r = r0 + half * 8;
            if (r < nrows) {
                float* cp = O + (size_t)r * ldc + colBase + nwarp * 32 + (lane & 3) * 2;
                #pragma unroll
                for (int nt = 0; nt < 4; nt++) {
                    float s0 = accW[mt][nt][half * 2];
                    float s1 = accW[mt][nt][half * 2 + 1];
                    float q0 = accG[mt][nt][half * 2];
                    float q1 = accG[mt][nt][half * 2 + 1];
                    float o0 = s0 / (1.f + expf(-q0));
                    float o1 = s1 / (1.f + expf(-q1));
                    if (RELU) { o0 = fmaxf(o0, 0.f); o1 = fmaxf(o1, 0.f); }
                    *(float2*)(cp + nt * 8) = make_float2(o0, o1);
                }
            }
        }
    }
}

// ---------------- launch ----------------
extern "C" void kernel_launch(void* const* d_in, const int* in_sizes, int n_in,
                              void* d_out, int out_size) {
    const float* x    = (const float*)d_in[0];
    const int*   rows = (const int*)  d_in[1];
    const int*   cols = (const int*)  d_in[2];
    const float* vals = (const float*)d_in[3];
    const float* W1   = (const float*)d_in[4];
    const float* G1   = (const float*)d_in[5];
    const float* W2   = (const float*)d_in[6];
    const float* G2   = (const float*)d_in[7];
    float* out2 = (float*)d_out;

    __nv_bfloat16 *p_z1h, *p_z1l, *p_z2h, *p_z2l;
    __nv_bfloat16 *p_w1h, *p_w1l, *p_g1h, *p_g1l, *p_w2h, *p_w2l, *p_g2h, *p_g2l;
    float* p_h;
    int *p_cnt, *p_cur, *p_rowptr;
    int2* p_ep;
    cudaGetSymbolAddress((void**)&p_z1h, g_z1h);
    cudaGetSymbolAddress((void**)&p_z1l, g_z1l);
    cudaGetSymbolAddress((void**)&p_z2h, g_z2h);
    cudaGetSymbolAddress((void**)&p_z2l, g_z2l);
    cudaGetSymbolAddress((void**)&p_h, g_h);
    cudaGetSymbolAddress((void**)&p_w1h, g_w1h);
    cudaGetSymbolAddress((void**)&p_w1l, g_w1l);
    cudaGetSymbolAddress((void**)&p_g1h, g_g1h);
    cudaGetSymbolAddress((void**)&p_g1l, g_g1l);
    cudaGetSymbolAddress((void**)&p_w2h, g_w2h);
    cudaGetSymbolAddress((void**)&p_w2l, g_w2l);
    cudaGetSymbolAddress((void**)&p_g2h, g_g2h);
    cudaGetSymbolAddress((void**)&p_g2l, g_g2l);
    cudaGetSymbolAddress((void**)&p_cnt, g_cnt);
    cudaGetSymbolAddress((void**)&p_cur, g_cur);
    cudaGetSymbolAddress((void**)&p_rowptr, g_rowptr);
    cudaGetSymbolAddress((void**)&p_ep, g_epack);

    cudaFuncSetAttribute(gemm_dual<true>, cudaFuncAttributeMaxDynamicSharedMemorySize, 2 * STAGE_B);
    cudaFuncSetAttribute(gemm_dual<false>, cudaFuncAttributeMaxDynamicSharedMemorySize, 2 * STAGE_B);

    // --- CSR build ---
    zero_counters<<<(N_NODES + 255) / 256, 256>>>(p_cnt, p_cur);
    hist_kernel<<<(E_EDGES + 255) / 256, 256>>>(rows, p_cnt);
    scan_kernel<<<1, 1024>>>(p_cnt, p_rowptr);
    scatter_kernel<<<(E_EDGES + 255) / 256, 256>>>(rows, cols, vals, p_rowptr, p_cur, p_ep);

    // --- weight transpose + split ---
    split_w_kernel<<<(D_IN * D_HID + 255) / 256, 256>>>(W1, p_w1h, p_w1l, D_IN, D_HID);
    split_w_kernel<<<(D_IN * D_HID + 255) / 256, 256>>>(G1, p_g1h, p_g1l, D_IN, D_HID);
    split_w_kernel<<<(D_HID * D_OUT_ + 255) / 256, 256>>>(W2, p_w2h, p_w2l, D_HID, D_OUT_);
    split_w_kernel<<<(D_HID * D_OUT_ + 255) / 256, 256>>>(G2, p_g2h, p_g2l, D_HID, D_OUT_);

    const int rt = (N_NODES + 127) / 128;  // 391

    // --- Z1 = A*x, split ---
    spmm_z<<<(N_NODES + 3) / 4, 256>>>(p_rowptr, p_ep, x, p_z1h, p_z1l);

    // --- h = relu(sigmoid(Z1@G1) * (Z1@W1)) ---
    gemm_dual<true><<<dim3(rt, D_HID / 64), 256, 2 * STAGE_B>>>(
        p_z1h, p_z1l, p_w1h, p_w1l, p_g1h, p_g1l, p_h, N_NODES, D_HID);

    // --- Z2 = A*h, split ---
    spmm_z<<<(N_NODES + 3) / 4, 256>>>(p_rowptr, p_ep, p_h, p_z2h, p_z2l);

    // --- logits = sigmoid(Z2@G2) * (Z2@W2) -> d_out ---
    gemm_dual<false><<<dim3(rt, D_OUT_ / 64), 256, 2 * STAGE_B>>>(
        p_z2h, p_z2l, p_w2h, p_w2l, p_g2h, p_g2l, out2, N_NODES, D_OUT_);
}

// round 7
// speedup vs baseline: 3.1435x; 1.0205x over previous
#include <cuda_runtime.h>
#include <cuda_bf16.h>
#include <math.h>
#include <stdint.h>

#define N_NODES 50000
#define E_EDGES 800000
#define D_IN    256
#define D_HID   256
#define D_OUT_  128

// ---------------- device scratch ----------------
__device__ __nv_bfloat16 g_z1h[N_NODES * 256];
__device__ __nv_bfloat16 g_z1l[N_NODES * 256];
__device__ float         g_h  [N_NODES * 256];
__device__ __nv_bfloat16 g_z2h[N_NODES * 256];
__device__ __nv_bfloat16 g_z2l[N_NODES * 256];
// weights transposed to [n][k], hi/lo split
__device__ __nv_bfloat16 g_w1h[D_HID * D_IN], g_w1l[D_HID * D_IN];
__device__ __nv_bfloat16 g_g1h[D_HID * D_IN], g_g1l[D_HID * D_IN];
__device__ __nv_bfloat16 g_w2h[D_OUT_ * D_HID], g_w2l[D_OUT_ * D_HID];
__device__ __nv_bfloat16 g_g2h[D_OUT_ * D_HID], g_g2l[D_OUT_ * D_HID];
// CSR scratch
__device__ int  g_cnt[N_NODES];
__device__ int  g_cur[N_NODES];
__device__ int  g_rowptr[N_NODES + 1];
__device__ int2 g_epack[E_EDGES];

// ---------------- PTX helpers (arch-portable sm_80+) ----------------
__device__ __forceinline__ uint32_t smem_u32(const void* p) {
    uint32_t a;
    asm("{ .reg .u64 t; cvta.to.shared.u64 t, %1; cvt.u32.u64 %0, t; }" : "=r"(a) : "l"(p));
    return a;
}
__device__ __forceinline__ void cp16(uint32_t dst, const void* src, uint32_t sz) {
    asm volatile("cp.async.cg.shared.global [%0], [%1], 16, %2;"
                 :: "r"(dst), "l"(src), "r"(sz) : "memory");
}
#define CP_COMMIT() asm volatile("cp.async.commit_group;" ::: "memory")
#define CP_WAIT0()  asm volatile("cp.async.wait_group 0;" ::: "memory")
#define LDSM4(r, addr) \
    asm volatile("ldmatrix.sync.aligned.m8n8.x4.shared.b16 {%0,%1,%2,%3}, [%4];" \
                 : "=r"((r)[0]), "=r"((r)[1]), "=r"((r)[2]), "=r"((r)[3]) : "r"(addr))
#define MMA16816(d, a, b) \
    asm volatile("mma.sync.aligned.m16n8k16.row.col.f32.bf16.bf16.f32 " \
                 "{%0,%1,%2,%3}, {%4,%5,%6,%7}, {%8,%9}, {%0,%1,%2,%3};" \
                 : "+f"((d)[0]), "+f"((d)[1]), "+f"((d)[2]), "+f"((d)[3]) \
                 : "r"((a)[0]), "r"((a)[1]), "r"((a)[2]), "r"((a)[3]), \
                   "r"((b)[0]), "r"((b)[1]))

// ---------------- CSR build ----------------
__global__ void zero_counters(int* __restrict__ cnt, int* __restrict__ cur) {
    int i = blockIdx.x * blockDim.x + threadIdx.x;
    if (i < N_NODES) { cnt[i] = 0; cur[i] = 0; }
}
__global__ void hist_kernel(const int* __restrict__ rows, int* __restrict__ cnt) {
    int e = blockIdx.x * blockDim.x + threadIdx.x;
    if (e < E_EDGES) atomicAdd(&cnt[rows[e]], 1);
}
__global__ void scan_kernel(const int* __restrict__ cnt, int* __restrict__ rowptr) {
    __shared__ int ssum[1024];
    const int tid = threadIdx.x;
    const int CH = (N_NODES + 1023) / 1024;
    int base = tid * CH;
    int s = 0;
    for (int i = 0; i < CH; i++) { int idx = base + i; if (idx < N_NODES) s += cnt[idx]; }
    ssum[tid] = s;
    __syncthreads();
    for (int off = 1; off < 1024; off <<= 1) {
        int v = 0;
        if (tid >= off) v = ssum[tid - off];
        __syncthreads();
        ssum[tid] += v;
        __syncthreads();
    }
    int prefix = (tid == 0) ? 0 : ssum[tid - 1];
    for (int i = 0; i < CH; i++) {
        int idx = base + i;
        if (idx < N_NODES) { rowptr[idx] = prefix; prefix += cnt[idx]; }
    }
    if (tid == 1023) rowptr[N_NODES] = prefix;
}
// 4 edges per thread: independent atomic chains for MLP
__global__ void scatter_kernel(const int* __restrict__ rows, const int* __restrict__ cols,
                               const float* __restrict__ vals,
                               const int* __restrict__ rowptr, int* __restrict__ cur,
                               int2* __restrict__ ep) {
    int base = (blockIdx.x * blockDim.x + threadIdx.x) * 4;
    #pragma unroll
    for (int j = 0; j < 4; j++) {
        int e = base + j;
        if (e < E_EDGES) {
            int r = __ldg(&rows[e]);
            int pos = rowptr[r] + atomicAdd(&cur[r], 1);
            ep[pos] = make_int2(__ldg(&cols[e]), __float_as_int(__ldg(&vals[e])));
        }
    }
}

// ---------------- all-weight transpose + split (one kernel) ----------------
// W1,G1: 256x256 each; W2,G2: 256x128 each. Total 196608 elements.
__global__ void split_all_w(const float* __restrict__ W1, const float* __restrict__ G1,
                            const float* __restrict__ W2, const float* __restrict__ G2,
                            __nv_bfloat16* __restrict__ w1h, __nv_bfloat16* __restrict__ w1l,
                            __nv_bfloat16* __restrict__ g1h, __nv_bfloat16* __restrict__ g1l,
                            __nv_bfloat16* __restrict__ w2h, __nv_bfloat16* __restrict__ w2l,
                            __nv_bfloat16* __restrict__ g2h, __nv_bfloat16* __restrict__ g2l) {
    int i = blockIdx.x * blockDim.x + threadIdx.x;
    const int S1 = 256 * 256;              // per layer-1 matrix
    const int S2 = 256 * 128;              // per layer-2 matrix
    const float* src;
    __nv_bfloat16 *oh, *ol;
    int idx, M;
    if (i < S1)                { src = W1; oh = w1h; ol = w1l; idx = i;            M = 256; }
    else if (i < 2 * S1)       { src = G1; oh = g1h; ol = g1l; idx = i - S1;       M = 256; }
    else if (i < 2 * S1 + S2)  { src = W2; oh = w2h; ol = w2l; idx = i - 2 * S1;   M = 128; }
    else if (i < 2 * S1 + 2*S2){ src = G2; oh = g2h; ol = g2l; idx = i - 2*S1 - S2; M = 128; }
    else return;
    int n = idx / 256, k = idx % 256;      // out[n*256+k] = in[k*M+n]
    float v = src[(size_t)k * M + n];
    __nv_bfloat16 h = __float2bfloat16(v);
    oh[idx] = h;
    ol[idx] = __float2bfloat16(v - __bfloat162float(h));
}

// ---------------- SpMM: Z = A * src (D=256), unroll x4, dual accumulators ----
__global__ void __launch_bounds__(256)
spmm_z(const int* __restrict__ rowptr, const int2* __restrict__ ep,
       const float* __restrict__ src,
       __nv_bfloat16* __restrict__ zh, __nv_bfloat16* __restrict__ zl) {
    const int lane = threadIdx.x & 63;
    const int row = blockIdx.x * 4 + (threadIdx.x >> 6);
    if (row >= N_NODES) return;
    const int c = lane * 4;

    int e    = __ldg(&rowptr[row]);
    int eend = __ldg(&rowptr[row + 1]);
    float4 a0 = make_float4(0.f, 0.f, 0.f, 0.f);
    float4 a1 = a0;

    for (; e + 4 <= eend; e += 4) {
        int2 e0 = __ldg(&ep[e]);
        int2 e1 = __ldg(&ep[e + 1]);
        int2 e2 = __ldg(&ep[e + 2]);
        int2 e3 = __ldg(&ep[e + 3]);
        float4 s0 = *(const float4*)&src[(size_t)e0.x * 256 + c];
        float4 s1 = *(const float4*)&src[(size_t)e1.x * 256 + c];
        float4 s2 = *(const float4*)&src[(size_t)e2.x * 256 + c];
        float4 s3 = *(const float4*)&src[(size_t)e3.x * 256 + c];
        float v0 = __int_as_float(e0.y), v1 = __int_as_float(e1.y);
        float v2 = __int_as_float(e2.y), v3 = __int_as_float(e3.y);
        a0.x = fmaf(v0, s0.x, a0.x); a0.y = fmaf(v0, s0.y, a0.y);
        a0.z = fmaf(v0, s0.z, a0.z); a0.w = fmaf(v0, s0.w, a0.w);
        a1.x = fmaf(v1, s1.x, a1.x); a1.y = fmaf(v1, s1.y, a1.y);
        a1.z = fmaf(v1, s1.z, a1.z); a1.w = fmaf(v1, s1.w, a1.w);
        a0.x = fmaf(v2, s2.x, a0.x); a0.y = fmaf(v2, s2.y, a0.y);
        a0.z = fmaf(v2, s2.z, a0.z); a0.w = fmaf(v2, s2.w, a0.w);
        a1.x = fmaf(v3, s3.x, a1.x); a1.y = fmaf(v3, s3.y, a1.y);
        a1.z = fmaf(v3, s3.z, a1.z); a1.w = fmaf(v3, s3.w, a1.w);
    }
    for (; e < eend; e++) {
        int2 ev = __ldg(&ep[e]);
        float v = __int_as_float(ev.y);
        const float4 sv = *(const float4*)&src[(size_t)ev.x * 256 + c];
        a0.x = fmaf(v, sv.x, a0.x); a0.y = fmaf(v, sv.y, a0.y);
        a0.z = fmaf(v, sv.z, a0.z); a0.w = fmaf(v, sv.w, a0.w);
    }
    float o[4] = {a0.x + a1.x, a0.y + a1.y, a0.z + a1.z, a0.w + a1.w};
    __nv_bfloat16 h[4], l[4];
    #pragma unroll
    for (int j = 0; j < 4; j++) {
        h[j] = __float2bfloat16(o[j]);
        l[j] = __float2bfloat16(o[j] - __bfloat162float(h[j]));
    }
    *(uint2*)&zh[(size_t)row * 256 + c] = *(uint2*)h;
    *(uint2*)&zl[(size_t)row * 256 + c] = *(uint2*)l;
}

// ---------------- fused dual GEMM + gating epilogue ----------------
// Block 128(M) x 64(N); 8 warps = 4M x 2N; 3-term bf16 split for both W and G paths.
#define STAGE_B 40960

template <bool RELU>
__global__ void __launch_bounds__(256)
gemm_dual(const __nv_bfloat16* __restrict__ Ah, const __nv_bfloat16* __restrict__ Al,
          const __nv_bfloat16* __restrict__ BWh, const __nv_bfloat16* __restrict__ BWl,
          const __nv_bfloat16* __restrict__ BGh, const __nv_bfloat16* __restrict__ BGl,
          float* __restrict__ O, int nrows, int ldc) {
    extern __shared__ __align__(128) char smem[];
    const int tid  = threadIdx.x;
    const int lane = tid & 31;
    const int wid  = tid >> 5;
    const int mwarp = wid >> 1;
    const int nwarp = wid & 1;
    const int rowBase = blockIdx.x * 128;
    const int colBase = blockIdx.y * 64;
    const uint32_t sb = smem_u32(smem);

    const uint32_t AH = 0, AL = 10240, WH = 20480, WL = 25600, GH = 30720, GL = 35840;

    float accW[2][4][4] = {};
    float accG[2][4][4] = {};

    auto load_stage = [&](int s, int k0) {
        uint32_t base = sb + s * STAGE_B;
        int r = tid >> 2;
        int c = tid & 3;
        uint32_t ro = r * 80 + c * 16;
        #pragma unroll
        for (int half = 0; half < 2; half++) {
            int row = r + half * 64;
            uint32_t ro2 = row * 80 + c * 16;
            int gr = rowBase + row;
            uint32_t sz = (gr < nrows) ? 16u : 0u;
            size_t aoff = (size_t)gr * 256 + k0 + c * 8;
            cp16(base + AH + ro2, Ah + aoff, sz);
            cp16(base + AL + ro2, Al + aoff, sz);
        }
        {
            int gn = colBase + r;
            size_t boff = (size_t)gn * 256 + k0 + c * 8;
            cp16(base + WH + ro, BWh + boff, 16);
            cp16(base + WL + ro, BWl + boff, 16);
            cp16(base + GH + ro, BGh + boff, 16);
            cp16(base + GL + ro, BGl + boff, 16);
        }
        CP_COMMIT();
    };

    auto do_mma = [&](float (&acc)[2][4][4], uint32_t (&a)[8], uint32_t (&b)[8]) {
        #pragma unroll
        for (int mt = 0; mt < 2; mt++)
            #pragma unroll
            for (int nt = 0; nt < 4; nt++)
                MMA16816(acc[mt][nt], &a[mt * 4], &b[(nt >> 1) * 4 + (nt & 1) * 2]);
    };

    load_stage(0, 0);

    for (int ch = 0; ch < 8; ch++) {
        CP_WAIT0();
        __syncthreads();
        if (ch < 7) load_stage((ch + 1) & 1, (ch + 1) * 32);

        uint32_t base = sb + (ch & 1) * STAGE_B;
        #pragma unroll
        for (int j = 0; j < 2; j++) {
            uint32_t ah[8], al[8], bb[8];
            uint32_t aoffb = (mwarp * 32 + (lane & 15)) * 80 + (j * 2 + (lane >> 4)) * 16;
            uint32_t boffb = (nwarp * 32 + (lane & 7) + ((lane >> 4) << 3)) * 80 +
                             (j * 2 + ((lane >> 3) & 1)) * 16;

            LDSM4(&ah[0], base + AH + aoffb);
            LDSM4(&ah[4], base + AH + aoffb + 16 * 80);
            LDSM4(&bb[0], base + WH + boffb);
            LDSM4(&bb[4], base + WH + boffb + 16 * 80);
            do_mma(accW, ah, bb);                      // Ah*Wh
            LDSM4(&al[0], base + AL + aoffb);
            LDSM4(&al[4], base + AL + aoffb + 16 * 80);
            do_mma(accW, al, bb);                      // Al*Wh
            LDSM4(&bb[0], base + WL + boffb);
            LDSM4(&bb[4], base + WL + boffb + 16 * 80);
            do_mma(accW, ah, bb);                      // Ah*Wl
            LDSM4(&bb[0], base + GH + boffb);
            LDSM4(&bb[4], base + GH + boffb + 16 * 80);
            do_mma(accG, ah, bb);                      // Ah*Gh
            do_mma(accG, al, bb);                      // Al*Gh
            LDSM4(&bb[0], base + GL + boffb);
            LDSM4(&bb[4], base + GL + boffb + 16 * 80);
            do_mma(accG, ah, bb);                      // Ah*Gl
        }
        __syncthreads();
    }

    #pragma unroll
    for (int mt = 0; mt < 2; mt++) {
        int r0 = rowBase + mwarp * 32 + mt * 16 + (lane >> 2);
        #pragma unroll
        for (int half = 0; half < 2; half++) {
            int r = r0 + half * 8;
            if (r < nrows) {
                float* cp = O + (size_t)r * ldc + colBase + nwarp * 32 + (lane & 3) * 2;
                #pragma unroll
                for (int nt = 0; nt < 4; nt++) {
                    float s0 = accW[mt][nt][half * 2];
                    float s1 = accW[mt][nt][half * 2 + 1];
                    float q0 = accG[mt][nt][half * 2];
                    float q1 = accG[mt][nt][half * 2 + 1];
                    float o0 = s0 / (1.f + expf(-q0));
                    float o1 = s1 / (1.f + expf(-q1));
                    if (RELU) { o0 = fmaxf(o0, 0.f); o1 = fmaxf(o1, 0.f); }
                    *(float2*)(cp + nt * 8) = make_float2(o0, o1);
                }
            }
        }
    }
}

// ---------------- launch ----------------
extern "C" void kernel_launch(void* const* d_in, const int* in_sizes, int n_in,
                              void* d_out, int out_size) {
    const float* x    = (const float*)d_in[0];
    const int*   rows = (const int*)  d_in[1];
    const int*   cols = (const int*)  d_in[2];
    const float* vals = (const float*)d_in[3];
    const float* W1   = (const float*)d_in[4];
    const float* G1   = (const float*)d_in[5];
    const float* W2   = (const float*)d_in[6];
    const float* G2   = (const float*)d_in[7];
    float* out2 = (float*)d_out;

    __nv_bfloat16 *p_z1h, *p_z1l, *p_z2h, *p_z2l;
    __nv_bfloat16 *p_w1h, *p_w1l, *p_g1h, *p_g1l, *p_w2h, *p_w2l, *p_g2h, *p_g2l;
    float* p_h;
    int *p_cnt, *p_cur, *p_rowptr;
    int2* p_ep;
    cudaGetSymbolAddress((void**)&p_z1h, g_z1h);
    cudaGetSymbolAddress((void**)&p_z1l, g_z1l);
    cudaGetSymbolAddress((void**)&p_z2h, g_z2h);
    cudaGetSymbolAddress((void**)&p_z2l, g_z2l);
    cudaGetSymbolAddress((void**)&p_h, g_h);
    cudaGetSymbolAddress((void**)&p_w1h, g_w1h);
    cudaGetSymbolAddress((void**)&p_w1l, g_w1l);
    cudaGetSymbolAddress((void**)&p_g1h, g_g1h);
    cudaGetSymbolAddress((void**)&p_g1l, g_g1l);
    cudaGetSymbolAddress((void**)&p_w2h, g_w2h);
    cudaGetSymbolAddress((void**)&p_w2l, g_w2l);
    cudaGetSymbolAddress((void**)&p_g2h, g_g2h);
    cudaGetSymbolAddress((void**)&p_g2l, g_g2l);
    cudaGetSymbolAddress((void**)&p_cnt, g_cnt);
    cudaGetSymbolAddress((void**)&p_cur, g_cur);
    cudaGetSymbolAddress((void**)&p_rowptr, g_rowptr);
    cudaGetSymbolAddress((void**)&p_ep, g_epack);

    cudaFuncSetAttribute(gemm_dual<true>, cudaFuncAttributeMaxDynamicSharedMemorySize, 2 * STAGE_B);
    cudaFuncSetAttribute(gemm_dual<false>, cudaFuncAttributeMaxDynamicSharedMemorySize, 2 * STAGE_B);

    // --- CSR build ---
    zero_counters<<<(N_NODES + 255) / 256, 256>>>(p_cnt, p_cur);
    hist_kernel<<<(E_EDGES + 255) / 256, 256>>>(rows, p_cnt);
    scan_kernel<<<1, 1024>>>(p_cnt, p_rowptr);
    scatter_kernel<<<(E_EDGES / 4 + 255) / 256, 256>>>(rows, cols, vals, p_rowptr, p_cur, p_ep);

    // --- all weight transposes + splits in one kernel ---
    {
        int tot = 2 * 256 * 256 + 2 * 256 * 128;
        split_all_w<<<(tot + 255) / 256, 256>>>(W1, G1, W2, G2,
                                                p_w1h, p_w1l, p_g1h, p_g1l,
                                                p_w2h, p_w2l, p_g2h, p_g2l);
    }

    const int rt = (N_NODES + 127) / 128;  // 391

    // --- Z1 = A*x, split ---
    spmm_z<<<(N_NODES + 3) / 4, 256>>>(p_rowptr, p_ep, x, p_z1h, p_z1l);

    // --- h = relu(sigmoid(Z1@G1) * (Z1@W1)) ---
    gemm_dual<true><<<dim3(rt, D_HID / 64), 256, 2 * STAGE_B>>>(
        p_z1h, p_z1l, p_w1h, p_w1l, p_g1h, p_g1l, p_h, N_NODES, D_HID);

    // --- Z2 = A*h, split ---
    spmm_z<<<(N_NODES + 3) / 4, 256>>>(p_rowptr, p_ep, p_h, p_z2h, p_z2l);

    // --- logits = sigmoid(Z2@G2) * (Z2@W2) -> d_out ---
    gemm_dual<false><<<dim3(rt, D_OUT_ / 64), 256, 2 * STAGE_B>>>(
        p_z2h, p_z2l, p_w2h, p_w2l, p_g2h, p_g2l, out2, N_NODES, D_OUT_);
}